// round 1
// baseline (speedup 1.0000x reference)
#include <cuda_runtime.h>
#include <cuda_bf16.h>
#include <math.h>

#define ENT 250000
#define RELN 64
#define D 128
#define BB 32768
#define KK 8
#define NNEG (BB*KK)

#define ROWS_PER_BLK 1024
#define HBLK_POS (BB/ROWS_PER_BLK)    // 32
#define HBLK_NEG (NNEG/ROWS_PER_BLK)  // 256

// Scratch (device globals: no allocations allowed)
__device__ unsigned char g_br_pos[BB];
__device__ unsigned char g_br_neg[NNEG];
__device__ int g_sp_pos[BB];
__device__ int g_sp_neg[NNEG];
__device__ int g_hist_pos[HBLK_POS*4];
__device__ int g_hist_neg[HBLK_NEG*4];
__device__ int g_off_pos[HBLK_POS*4];
__device__ int g_off_neg[HBLK_NEG*4];

__global__ void k_zero(float* out) {
    int i = blockIdx.x*blockDim.x + threadIdx.x;
    if (i < BB) out[i] = 0.0f;
}

// ---- branch + histogram ----
__global__ void k_branch_pos(const int* __restrict__ inl, const int* __restrict__ pl) {
    __shared__ int h[4];
    int t = threadIdx.x;
    if (t < 4) h[t] = 0;
    __syncthreads();
    int row = blockIdx.x*ROWS_PER_BLK + t;
    int c = ((inl[row] >= ENT) ? 2 : 0) + ((pl[row] >= ENT) ? 1 : 0);
    g_br_pos[row] = (unsigned char)c;
    atomicAdd(&h[c], 1);
    __syncthreads();
    if (t < 4) g_hist_pos[blockIdx.x*4 + t] = h[t];
}

__global__ void k_branch_neg(const int* __restrict__ inl, const int* __restrict__ nl) {
    __shared__ int h[4];
    int t = threadIdx.x;
    if (t < 4) h[t] = 0;
    __syncthreads();
    int row = blockIdx.x*ROWS_PER_BLK + t;
    int i = row >> 3;
    int c = ((inl[i] >= ENT) ? 2 : 0) + ((nl[row] >= ENT) ? 1 : 0);
    g_br_neg[row] = (unsigned char)c;
    atomicAdd(&h[c], 1);
    __syncthreads();
    if (t < 4) g_hist_neg[blockIdx.x*4 + t] = h[t];
}

// ---- single-block scan over per-block histograms: off[b][c] = classBase[c] + sum_{b'<b} hist[b'][c] ----
__global__ void k_scan(const int* __restrict__ hist, int* __restrict__ off, int nblk) {
    __shared__ int s[256];
    int t = threadIdx.x;
    int exc[4], tot[4];
    for (int c = 0; c < 4; c++) {
        int v = (t < nblk) ? hist[t*4 + c] : 0;
        s[t] = v;
        __syncthreads();
        for (int d = 1; d < 256; d <<= 1) {
            int u = (t >= d) ? s[t - d] : 0;
            __syncthreads();
            s[t] += u;
            __syncthreads();
        }
        exc[c] = s[t] - v;
        tot[c] = s[nblk - 1];
        __syncthreads();
    }
    int base = 0, baseC[4];
    for (int c = 0; c < 4; c++) { baseC[c] = base; base += tot[c]; }
    if (t < nblk)
        for (int c = 0; c < 4; c++) off[t*4 + c] = baseC[c] + exc[c];
}

// ---- stable intra-block rank via packed 4x16-bit scan ----
__global__ void k_rank(const unsigned char* __restrict__ br, const int* __restrict__ off,
                       int* __restrict__ sp) {
    __shared__ unsigned long long s[ROWS_PER_BLK];
    int t = threadIdx.x;
    int row = blockIdx.x*ROWS_PER_BLK + t;
    int c = br[row];
    unsigned long long v = 1ULL << (c*16);
    s[t] = v;
    __syncthreads();
    for (int d = 1; d < ROWS_PER_BLK; d <<= 1) {
        unsigned long long u = (t >= d) ? s[t - d] : 0ULL;
        __syncthreads();
        s[t] += u;
        __syncthreads();
    }
    int rank = (int)((  (s[t] - v) >> (c*16)) & 0xFFFFULL);
    sp[row] = off[blockIdx.x*4 + c] + rank;
}

// ---- dot kernel: one warp per row ----
__device__ __forceinline__ float warpsum(float v) {
    v += __shfl_xor_sync(0xFFFFFFFFu, v, 16);
    v += __shfl_xor_sync(0xFFFFFFFFu, v, 8);
    v += __shfl_xor_sync(0xFFFFFFFFu, v, 4);
    v += __shfl_xor_sync(0xFFFFFFFFu, v, 2);
    v += __shfl_xor_sync(0xFFFFFFFFu, v, 1);
    return v;
}

__device__ __forceinline__ float4 ld4(const float* base, int lane) {
    return reinterpret_cast<const float4*>(base)[lane];
}

// TransH projection: e - (e.n) n with n = m / max(||m||, 1e-12)
__device__ __forceinline__ float4 map4(float4 e, float4 m) {
    float mm = m.x*m.x + m.y*m.y + m.z*m.z + m.w*m.w;
    float em = e.x*m.x + e.y*m.y + e.z*m.z + e.w*m.w;
    mm = warpsum(mm);
    em = warpsum(em);
    float dn = fmaxf(sqrtf(mm), 1e-12f);
    float coef = em / (dn*dn);
    float4 r;
    r.x = e.x - coef*m.x;
    r.y = e.y - coef*m.y;
    r.z = e.z - coef*m.z;
    r.w = e.w - coef*m.w;
    return r;
}

__global__ void __launch_bounds__(256) k_dot(
    const float* __restrict__ ie, const float* __restrict__ oe,
    const float* __restrict__ ir, const float* __restrict__ orr,
    const float* __restrict__ im, const float* __restrict__ om,
    const int* __restrict__ inl, const int* __restrict__ pl, const int* __restrict__ nl,
    float* __restrict__ out)
{
    int gw = (blockIdx.x*blockDim.x + threadIdx.x) >> 5;
    int lane = threadIdx.x & 31;
    bool is_pos = (gw < BB);
    int i, plab;
    if (is_pos) { i = gw; plab = pl[gw]; }
    else        { int r = gw - BB; i = r >> 3; plab = nl[r]; }
    int ilab = inl[i];
    bool ei = ilab < ENT, ep = plab < ENT;
    int iid = ei ? ilab : (ilab - ENT);
    int pid = ep ? plab : (plab - ENT);
    int iid_r = min(iid, RELN - 1);
    int pid_r = min(pid, RELN - 1);

    float4 inp;
    if (!ei) {
        inp = ld4(ir + iid_r*D, lane);
    } else if (ep) {
        inp = ld4(ie + (long)iid*D, lane);
    } else {
        float4 e = ld4(ie + (long)iid*D, lane);
        float4 m = ld4(im + pid_r*D, lane);
        inp = map4(e, m);
    }

    float4 ou;
    if (!ep) {
        ou = ld4(orr + pid_r*D, lane);
    } else if (ei) {
        ou = ld4(oe + (long)pid*D, lane);
    } else {
        float4 e = ld4(oe + (long)pid*D, lane);
        float4 m = ld4(om + iid_r*D, lane);
        ou = map4(e, m);
    }

    float d = inp.x*ou.x + inp.y*ou.y + inp.z*ou.z + inp.w*ou.w;
    d = warpsum(d);

    if (lane == 0) {
        float x = is_pos ? d : -d;
        float ls = fminf(x, 0.0f) - log1pf(expf(-fabsf(x)));
        int tgt = is_pos ? g_sp_pos[gw] : (g_sp_neg[gw - BB] >> 3);
        atomicAdd(&out[tgt], -ls);
    }
}

extern "C" void kernel_launch(void* const* d_in, const int* in_sizes, int n_in,
                              void* d_out, int out_size)
{
    const float* ie  = (const float*)d_in[0];  // in_ent_w
    const float* oe  = (const float*)d_in[1];  // out_ent_w
    const float* ir  = (const float*)d_in[2];  // in_rel_w
    const float* orr = (const float*)d_in[3];  // out_rel_w
    const float* im  = (const float*)d_in[4];  // in_map_w
    const float* om  = (const float*)d_in[5];  // out_map_w
    const int* inl = (const int*)d_in[6];      // input_labels
    const int* pl  = (const int*)d_in[7];      // pos_labels
    const int* nl  = (const int*)d_in[8];      // neg_labels (B*K)
    float* out = (float*)d_out;

    k_zero<<<(BB + 255)/256, 256>>>(out);

    k_branch_pos<<<HBLK_POS, ROWS_PER_BLK>>>(inl, pl);
    k_branch_neg<<<HBLK_NEG, ROWS_PER_BLK>>>(inl, nl);

    int *hist_pos, *hist_neg, *off_pos, *off_neg;
    cudaGetSymbolAddress((void**)&hist_pos, g_hist_pos);
    cudaGetSymbolAddress((void**)&hist_neg, g_hist_neg);
    cudaGetSymbolAddress((void**)&off_pos, g_off_pos);
    cudaGetSymbolAddress((void**)&off_neg, g_off_neg);
    unsigned char *br_pos, *br_neg;
    int *sp_pos, *sp_neg;
    cudaGetSymbolAddress((void**)&br_pos, g_br_pos);
    cudaGetSymbolAddress((void**)&br_neg, g_br_neg);
    cudaGetSymbolAddress((void**)&sp_pos, g_sp_pos);
    cudaGetSymbolAddress((void**)&sp_neg, g_sp_neg);

    k_scan<<<1, 256>>>(hist_pos, off_pos, HBLK_POS);
    k_scan<<<1, 256>>>(hist_neg, off_neg, HBLK_NEG);

    k_rank<<<HBLK_POS, ROWS_PER_BLK>>>(br_pos, off_pos, sp_pos);
    k_rank<<<HBLK_NEG, ROWS_PER_BLK>>>(br_neg, off_neg, sp_neg);

    int total_rows = BB + NNEG;               // 294912 warps
    int blocks = total_rows / 8;              // 8 warps (256 threads) per block
    k_dot<<<blocks, 256>>>(ie, oe, ir, orr, im, om, inl, pl, nl, out);
}

// round 2
// speedup vs baseline: 1.1703x; 1.1703x over previous
#include <cuda_runtime.h>
#include <cuda_bf16.h>
#include <math.h>

#define ENT 250000
#define RELN 64
#define D 128
#define BB 32768
#define KK 8
#define NNEG (BB*KK)

#define ROWS_PER_BLK 1024
#define HBLK_POS (BB/ROWS_PER_BLK)    // 32
#define HBLK_NEG (NNEG/ROWS_PER_BLK)  // 256

// Scratch (device globals: no allocations allowed)
// packed per-row: (class << 12) | local_rank   (local_rank < 1024)
__device__ unsigned short g_cr_pos[BB];
__device__ unsigned short g_cr_neg[NNEG];
__device__ int g_hist_pos[HBLK_POS*4];
__device__ int g_hist_neg[HBLK_NEG*4];
__device__ int g_off_pos[HBLK_POS*4];
__device__ int g_off_neg[HBLK_NEG*4];

// ---------------------------------------------------------------------------
// K1: branch classification + per-block stable rank + per-block histogram.
// Blocks [0, HBLK_POS) handle pos rows (and zero `out` for free);
// blocks [HBLK_POS, HBLK_POS+HBLK_NEG) handle neg rows.
// ---------------------------------------------------------------------------
__global__ void __launch_bounds__(ROWS_PER_BLK) k_prep(
    const int* __restrict__ inl, const int* __restrict__ pl,
    const int* __restrict__ nl, float* __restrict__ out)
{
    int blk = blockIdx.x;
    bool is_pos = (blk < HBLK_POS);
    int t = threadIdx.x;
    int lane = t & 31, warp = t >> 5;

    int row, c;
    if (is_pos) {
        row = blk*ROWS_PER_BLK + t;
        out[row] = 0.0f;   // fused zeroing of the 32768-elem output
        c = ((inl[row] >= ENT) ? 2 : 0) + ((pl[row] >= ENT) ? 1 : 0);
    } else {
        row = (blk - HBLK_POS)*ROWS_PER_BLK + t;
        c = ((inl[row >> 3] >= ENT) ? 2 : 0) + ((nl[row] >= ENT) ? 1 : 0);
    }

    // warp-level stable rank within class via ballots
    unsigned b0 = __ballot_sync(0xFFFFFFFFu, c & 1);
    unsigned b1 = __ballot_sync(0xFFFFFFFFu, c & 2);
    unsigned m  = ((c & 1) ? b0 : ~b0) & ((c & 2) ? b1 : ~b1);
    int rank_w  = __popc(m & ((1u << lane) - 1u));

    __shared__ int wcnt[32][4];
    __shared__ int woff[32][4];
    __shared__ int tot[4];
    if (lane < 4) {
        int cc = lane;
        unsigned mm = ((cc & 1) ? b0 : ~b0) & ((cc & 2) ? b1 : ~b1);
        wcnt[warp][cc] = __popc(mm);
    }
    __syncthreads();
    // warps 0..3: shuffle-scan the 32 per-warp counts of class==warp
    if (warp < 4) {
        int v = wcnt[lane][warp];
        int s = v;
        #pragma unroll
        for (int d = 1; d < 32; d <<= 1) {
            int u = __shfl_up_sync(0xFFFFFFFFu, s, d);
            if (lane >= d) s += u;
        }
        woff[lane][warp] = s - v;         // exclusive prefix
        if (lane == 31) tot[warp] = s;    // block total per class
    }
    __syncthreads();

    int lrank = woff[warp][c] + rank_w;
    unsigned short packed = (unsigned short)((c << 12) | lrank);
    if (is_pos) {
        g_cr_pos[row] = packed;
        if (t < 4) g_hist_pos[blk*4 + t] = tot[t];
    } else {
        g_cr_neg[row] = packed;
        if (t < 4) g_hist_neg[(blk - HBLK_POS)*4 + t] = tot[t];
    }
}

// ---------------------------------------------------------------------------
// K2: one block scans BOTH histogram sets.
// Neg: 256 blocks x 4 classes, packed 2 classes per u64 (32-bit lanes).
// Pos: 32 blocks, done by warp 0 afterwards.
// ---------------------------------------------------------------------------
__global__ void __launch_bounds__(256) k_scan2()
{
    int t = threadIdx.x, lane = t & 31, w = t >> 5;
    typedef unsigned long long u64;

    // ---- neg (256 entries) ----
    unsigned h0 = g_hist_neg[t*4+0], h1 = g_hist_neg[t*4+1];
    unsigned h2 = g_hist_neg[t*4+2], h3 = g_hist_neg[t*4+3];
    u64 ownA = (u64)h0 | ((u64)h1 << 32);
    u64 ownB = (u64)h2 | ((u64)h3 << 32);
    u64 A = ownA, B = ownB;
    #pragma unroll
    for (int d = 1; d < 32; d <<= 1) {
        u64 ua = __shfl_up_sync(0xFFFFFFFFu, A, d);
        u64 ub = __shfl_up_sync(0xFFFFFFFFu, B, d);
        if (lane >= d) { A += ua; B += ub; }
    }
    __shared__ u64 sA[8], sB[8];
    __shared__ u64 gTotA, gTotB;
    if (lane == 31) { sA[w] = A; sB[w] = B; }
    __syncthreads();
    if (t == 0) {
        u64 a = 0, b = 0;
        #pragma unroll
        for (int i = 0; i < 8; i++) {
            u64 ta = sA[i], tb = sB[i];
            sA[i] = a; sB[i] = b;
            a += ta; b += tb;
        }
        gTotA = a; gTotB = b;
    }
    __syncthreads();
    u64 excA = A + sA[w] - ownA;
    u64 excB = B + sB[w] - ownB;
    {
        unsigned n0 = (unsigned)(gTotA), n1 = (unsigned)(gTotA >> 32);
        unsigned n2 = (unsigned)(gTotB);
        int base0 = 0;
        int base1 = base0 + (int)n0;
        int base2 = base1 + (int)n1;
        int base3 = base2 + (int)n2;
        g_off_neg[t*4+0] = base0 + (int)(excA & 0xFFFFFFFFULL);
        g_off_neg[t*4+1] = base1 + (int)(excA >> 32);
        g_off_neg[t*4+2] = base2 + (int)(excB & 0xFFFFFFFFULL);
        g_off_neg[t*4+3] = base3 + (int)(excB >> 32);
    }

    // ---- pos (32 entries), warp 0 only ----
    if (w == 0) {
        unsigned p0 = g_hist_pos[lane*4+0], p1 = g_hist_pos[lane*4+1];
        unsigned p2 = g_hist_pos[lane*4+2], p3 = g_hist_pos[lane*4+3];
        u64 oA = (u64)p0 | ((u64)p1 << 32);
        u64 oB = (u64)p2 | ((u64)p3 << 32);
        u64 PA = oA, PB = oB;
        #pragma unroll
        for (int d = 1; d < 32; d <<= 1) {
            u64 ua = __shfl_up_sync(0xFFFFFFFFu, PA, d);
            u64 ub = __shfl_up_sync(0xFFFFFFFFu, PB, d);
            if (lane >= d) { PA += ua; PB += ub; }
        }
        u64 tA = __shfl_sync(0xFFFFFFFFu, PA, 31);
        u64 tB = __shfl_sync(0xFFFFFFFFu, PB, 31);
        u64 eA = PA - oA, eB = PB - oB;
        unsigned q0 = (unsigned)tA, q1 = (unsigned)(tA >> 32), q2 = (unsigned)tB;
        int base0 = 0;
        int base1 = base0 + (int)q0;
        int base2 = base1 + (int)q1;
        int base3 = base2 + (int)q2;
        g_off_pos[lane*4+0] = base0 + (int)(eA & 0xFFFFFFFFULL);
        g_off_pos[lane*4+1] = base1 + (int)(eA >> 32);
        g_off_pos[lane*4+2] = base2 + (int)(eB & 0xFFFFFFFFULL);
        g_off_pos[lane*4+3] = base3 + (int)(eB >> 32);
    }
}

// ---------------------------------------------------------------------------
// K3: dot kernel — one warp per row, lane = one float4 of the 128-dim vector
// ---------------------------------------------------------------------------
__device__ __forceinline__ float warpsum(float v) {
    v += __shfl_xor_sync(0xFFFFFFFFu, v, 16);
    v += __shfl_xor_sync(0xFFFFFFFFu, v, 8);
    v += __shfl_xor_sync(0xFFFFFFFFu, v, 4);
    v += __shfl_xor_sync(0xFFFFFFFFu, v, 2);
    v += __shfl_xor_sync(0xFFFFFFFFu, v, 1);
    return v;
}

__device__ __forceinline__ float4 ld4(const float* base, int lane) {
    return reinterpret_cast<const float4*>(base)[lane];
}

// TransH projection: e - (e.n) n with n = m / max(||m||, 1e-12)
__device__ __forceinline__ float4 map4(float4 e, float4 m) {
    float mm = m.x*m.x + m.y*m.y + m.z*m.z + m.w*m.w;
    float em = e.x*m.x + e.y*m.y + e.z*m.z + e.w*m.w;
    mm = warpsum(mm);
    em = warpsum(em);
    float dn = fmaxf(sqrtf(mm), 1e-12f);
    float coef = em / (dn*dn);
    float4 r;
    r.x = e.x - coef*m.x;
    r.y = e.y - coef*m.y;
    r.z = e.z - coef*m.z;
    r.w = e.w - coef*m.w;
    return r;
}

__global__ void __launch_bounds__(256) k_dot(
    const float* __restrict__ ie, const float* __restrict__ oe,
    const float* __restrict__ ir, const float* __restrict__ orr,
    const float* __restrict__ im, const float* __restrict__ om,
    const int* __restrict__ inl, const int* __restrict__ pl, const int* __restrict__ nl,
    float* __restrict__ out)
{
    int gw = (blockIdx.x*blockDim.x + threadIdx.x) >> 5;
    int lane = threadIdx.x & 31;
    bool is_pos = (gw < BB);
    int i, plab;
    if (is_pos) { i = gw; plab = pl[gw]; }
    else        { int r = gw - BB; i = r >> 3; plab = nl[r]; }
    int ilab = inl[i];
    bool ei = ilab < ENT, ep = plab < ENT;
    int iid = ei ? ilab : (ilab - ENT);
    int pid = ep ? plab : (plab - ENT);
    int iid_r = min(iid, RELN - 1);
    int pid_r = min(pid, RELN - 1);

    float4 inp;
    if (!ei) {
        inp = ld4(ir + iid_r*D, lane);
    } else if (ep) {
        inp = ld4(ie + (long)iid*D, lane);
    } else {
        float4 e = ld4(ie + (long)iid*D, lane);
        float4 m = ld4(im + pid_r*D, lane);
        inp = map4(e, m);
    }

    float4 ou;
    if (!ep) {
        ou = ld4(orr + pid_r*D, lane);
    } else if (ei) {
        ou = ld4(oe + (long)pid*D, lane);
    } else {
        float4 e = ld4(oe + (long)pid*D, lane);
        float4 m = ld4(om + iid_r*D, lane);
        ou = map4(e, m);
    }

    float d = inp.x*ou.x + inp.y*ou.y + inp.z*ou.z + inp.w*ou.w;
    d = warpsum(d);

    if (lane == 0) {
        float x = is_pos ? d : -d;
        float ls = fminf(x, 0.0f) - log1pf(expf(-fabsf(x)));
        int tgt;
        if (is_pos) {
            unsigned v = g_cr_pos[gw];
            int c = v >> 12, lr = v & 0xFFF;
            tgt = g_off_pos[(gw >> 10)*4 + c] + lr;
        } else {
            int r = gw - BB;
            unsigned v = g_cr_neg[r];
            int c = v >> 12, lr = v & 0xFFF;
            int s = g_off_neg[(r >> 10)*4 + c] + lr;   // sorted neg position
            tgt = s >> 3;                               // reshape(b,k).sum(1)
        }
        atomicAdd(&out[tgt], -ls);
    }
}

extern "C" void kernel_launch(void* const* d_in, const int* in_sizes, int n_in,
                              void* d_out, int out_size)
{
    const float* ie  = (const float*)d_in[0];  // in_ent_w
    const float* oe  = (const float*)d_in[1];  // out_ent_w
    const float* ir  = (const float*)d_in[2];  // in_rel_w
    const float* orr = (const float*)d_in[3];  // out_rel_w
    const float* im  = (const float*)d_in[4];  // in_map_w
    const float* om  = (const float*)d_in[5];  // out_map_w
    const int* inl = (const int*)d_in[6];      // input_labels
    const int* pl  = (const int*)d_in[7];      // pos_labels
    const int* nl  = (const int*)d_in[8];      // neg_labels (B*K)
    float* out = (float*)d_out;

    k_prep<<<HBLK_POS + HBLK_NEG, ROWS_PER_BLK>>>(inl, pl, nl, out);
    k_scan2<<<1, 256>>>();

    int total_rows = BB + NNEG;               // 294912 warps
    int blocks = total_rows / 8;              // 8 warps (256 threads) per block
    k_dot<<<blocks, 256>>>(ie, oe, ir, orr, im, om, inl, pl, nl, out);
}

// round 3
// speedup vs baseline: 1.3215x; 1.1292x over previous
#include <cuda_runtime.h>
#include <cuda_bf16.h>
#include <math.h>

#define ENT 250000
#define RELN 64
#define D 128
#define BB 32768
#define KK 8
#define NNEG (BB*KK)

#define ROWS_PER_BLK 1024
#define HBLK_POS (BB/ROWS_PER_BLK)    // 32
#define HBLK_NEG (NNEG/ROWS_PER_BLK)  // 256

typedef unsigned long long u64;

// Scratch (device globals: no allocations allowed)
// packed per-row: (class << 12) | local_rank   (local_rank < 1024)
__device__ unsigned short g_cr_pos[BB];
__device__ unsigned short g_cr_neg[NNEG];
__device__ int g_hist_pos[HBLK_POS*4];
__device__ int g_hist_neg[HBLK_NEG*4];
__device__ int g_off_pos[HBLK_POS*4];
__device__ int g_off_neg[HBLK_NEG*4];

// ---------------------------------------------------------------------------
// K1: branch classification + per-block stable rank + per-block histogram.
// 256 threads/block, 4 rows/thread (1024 rows/block).
// Blocks [0, HBLK_POS) = pos rows (also zero `out`); rest = neg rows.
// ---------------------------------------------------------------------------
__global__ void __launch_bounds__(256) k_prep(
    const int* __restrict__ inl, const int* __restrict__ pl,
    const int* __restrict__ nl, float* __restrict__ out)
{
    int blk = blockIdx.x;
    bool is_pos = (blk < HBLK_POS);
    int t = threadIdx.x;
    int lane = t & 31, warp = t >> 5;

    int rowbase;
    int c[4];
    if (is_pos) {
        rowbase = blk*ROWS_PER_BLK + t*4;
        int4 il  = *reinterpret_cast<const int4*>(inl + rowbase);
        int4 plv = *reinterpret_cast<const int4*>(pl + rowbase);
        *reinterpret_cast<float4*>(out + rowbase) = make_float4(0.f,0.f,0.f,0.f);
        c[0] = ((il.x >= ENT) ? 2 : 0) + ((plv.x >= ENT) ? 1 : 0);
        c[1] = ((il.y >= ENT) ? 2 : 0) + ((plv.y >= ENT) ? 1 : 0);
        c[2] = ((il.z >= ENT) ? 2 : 0) + ((plv.z >= ENT) ? 1 : 0);
        c[3] = ((il.w >= ENT) ? 2 : 0) + ((plv.w >= ENT) ? 1 : 0);
    } else {
        rowbase = (blk - HBLK_POS)*ROWS_PER_BLK + t*4;
        int ilv = inl[rowbase >> 3];               // constant across the 4 rows
        int4 nlv = *reinterpret_cast<const int4*>(nl + rowbase);
        int ci = (ilv >= ENT) ? 2 : 0;
        c[0] = ci + ((nlv.x >= ENT) ? 1 : 0);
        c[1] = ci + ((nlv.y >= ENT) ? 1 : 0);
        c[2] = ci + ((nlv.z >= ENT) ? 1 : 0);
        c[3] = ci + ((nlv.w >= ENT) ? 1 : 0);
    }

    // per-thread packed class counts (4 classes x 16 bits)
    u64 cnt = 0;
    #pragma unroll
    for (int j = 0; j < 4; j++) cnt += 1ULL << (16*c[j]);

    // warp inclusive scan
    u64 s = cnt;
    #pragma unroll
    for (int d = 1; d < 32; d <<= 1) {
        u64 u = __shfl_up_sync(0xFFFFFFFFu, s, d);
        if (lane >= d) s += u;
    }
    u64 wexcl = s - cnt;

    __shared__ u64 wtot[8];
    __shared__ u64 wbase[8];
    __shared__ u64 btot;
    if (lane == 31) wtot[warp] = s;
    __syncthreads();
    if (t == 0) {
        u64 a = 0;
        #pragma unroll
        for (int i = 0; i < 8; i++) { u64 tv = wtot[i]; wbase[i] = a; a += tv; }
        btot = a;
    }
    __syncthreads();

    u64 excl = wexcl + wbase[warp];   // per-class exclusive offset for this thread

    // assign stable ranks to the 4 rows in order
    u64 outpk = 0;
    #pragma unroll
    for (int j = 0; j < 4; j++) {
        int cc = c[j];
        int rk = (int)((excl >> (16*cc)) & 0xFFFFULL);
        excl += 1ULL << (16*cc);
        outpk |= ((u64)((cc << 12) | rk)) << (16*j);
    }

    if (is_pos) {
        *reinterpret_cast<u64*>(g_cr_pos + rowbase) = outpk;
        if (t < 4) g_hist_pos[blk*4 + t] = (int)((btot >> (16*t)) & 0xFFFFULL);
    } else {
        *reinterpret_cast<u64*>(g_cr_neg + rowbase) = outpk;
        if (t < 4) g_hist_neg[(blk - HBLK_POS)*4 + t] = (int)((btot >> (16*t)) & 0xFFFFULL);
    }
}

// ---------------------------------------------------------------------------
// K2: one block scans BOTH histogram sets (neg: 256 entries, pos: 32).
// ---------------------------------------------------------------------------
__global__ void __launch_bounds__(256) k_scan2()
{
    int t = threadIdx.x, lane = t & 31, w = t >> 5;

    // ---- neg (256 entries) ----
    unsigned h0 = g_hist_neg[t*4+0], h1 = g_hist_neg[t*4+1];
    unsigned h2 = g_hist_neg[t*4+2], h3 = g_hist_neg[t*4+3];
    u64 ownA = (u64)h0 | ((u64)h1 << 32);
    u64 ownB = (u64)h2 | ((u64)h3 << 32);
    u64 A = ownA, B = ownB;
    #pragma unroll
    for (int d = 1; d < 32; d <<= 1) {
        u64 ua = __shfl_up_sync(0xFFFFFFFFu, A, d);
        u64 ub = __shfl_up_sync(0xFFFFFFFFu, B, d);
        if (lane >= d) { A += ua; B += ub; }
    }
    __shared__ u64 sA[8], sB[8];
    __shared__ u64 gTotA, gTotB;
    if (lane == 31) { sA[w] = A; sB[w] = B; }
    __syncthreads();
    if (t == 0) {
        u64 a = 0, b = 0;
        #pragma unroll
        for (int i = 0; i < 8; i++) {
            u64 ta = sA[i], tb = sB[i];
            sA[i] = a; sB[i] = b;
            a += ta; b += tb;
        }
        gTotA = a; gTotB = b;
    }
    __syncthreads();
    u64 excA = A + sA[w] - ownA;
    u64 excB = B + sB[w] - ownB;
    {
        unsigned n0 = (unsigned)(gTotA), n1 = (unsigned)(gTotA >> 32);
        unsigned n2 = (unsigned)(gTotB);
        int base0 = 0;
        int base1 = base0 + (int)n0;
        int base2 = base1 + (int)n1;
        int base3 = base2 + (int)n2;
        g_off_neg[t*4+0] = base0 + (int)(excA & 0xFFFFFFFFULL);
        g_off_neg[t*4+1] = base1 + (int)(excA >> 32);
        g_off_neg[t*4+2] = base2 + (int)(excB & 0xFFFFFFFFULL);
        g_off_neg[t*4+3] = base3 + (int)(excB >> 32);
    }

    // ---- pos (32 entries), warp 0 only ----
    if (w == 0) {
        unsigned p0 = g_hist_pos[lane*4+0], p1 = g_hist_pos[lane*4+1];
        unsigned p2 = g_hist_pos[lane*4+2], p3 = g_hist_pos[lane*4+3];
        u64 oA = (u64)p0 | ((u64)p1 << 32);
        u64 oB = (u64)p2 | ((u64)p3 << 32);
        u64 PA = oA, PB = oB;
        #pragma unroll
        for (int d = 1; d < 32; d <<= 1) {
            u64 ua = __shfl_up_sync(0xFFFFFFFFu, PA, d);
            u64 ub = __shfl_up_sync(0xFFFFFFFFu, PB, d);
            if (lane >= d) { PA += ua; PB += ub; }
        }
        u64 tA = __shfl_sync(0xFFFFFFFFu, PA, 31);
        u64 tB = __shfl_sync(0xFFFFFFFFu, PB, 31);
        u64 eA = PA - oA, eB = PB - oB;
        unsigned q0 = (unsigned)tA, q1 = (unsigned)(tA >> 32), q2 = (unsigned)tB;
        int base0 = 0;
        int base1 = base0 + (int)q0;
        int base2 = base1 + (int)q1;
        int base3 = base2 + (int)q2;
        g_off_pos[lane*4+0] = base0 + (int)(eA & 0xFFFFFFFFULL);
        g_off_pos[lane*4+1] = base1 + (int)(eA >> 32);
        g_off_pos[lane*4+2] = base2 + (int)(eB & 0xFFFFFFFFULL);
        g_off_pos[lane*4+3] = base3 + (int)(eB >> 32);
    }
}

// ---------------------------------------------------------------------------
// K3: dot kernel — one warp handles 4 rows (MLP=8 float4 gathers in flight)
// ---------------------------------------------------------------------------
__device__ __forceinline__ float warpsum(float v) {
    v += __shfl_xor_sync(0xFFFFFFFFu, v, 16);
    v += __shfl_xor_sync(0xFFFFFFFFu, v, 8);
    v += __shfl_xor_sync(0xFFFFFFFFu, v, 4);
    v += __shfl_xor_sync(0xFFFFFFFFu, v, 2);
    v += __shfl_xor_sync(0xFFFFFFFFu, v, 1);
    return v;
}

__device__ __forceinline__ float4 ld4(const float* base, int lane) {
    return reinterpret_cast<const float4*>(base)[lane];
}

// TransH projection: e - (e.n) n with n = m / max(||m||, 1e-12)
__device__ __forceinline__ float4 map4(float4 e, float4 m) {
    float mm = m.x*m.x + m.y*m.y + m.z*m.z + m.w*m.w;
    float em = e.x*m.x + e.y*m.y + e.z*m.z + e.w*m.w;
    mm = warpsum(mm);
    em = warpsum(em);
    float dn = fmaxf(sqrtf(mm), 1e-12f);
    float coef = em / (dn*dn);
    float4 r;
    r.x = e.x - coef*m.x;
    r.y = e.y - coef*m.y;
    r.z = e.z - coef*m.z;
    r.w = e.w - coef*m.w;
    return r;
}

__global__ void __launch_bounds__(256) k_dot(
    const float* __restrict__ ie, const float* __restrict__ oe,
    const float* __restrict__ ir, const float* __restrict__ orr,
    const float* __restrict__ im, const float* __restrict__ om,
    const int* __restrict__ inl, const int* __restrict__ pl, const int* __restrict__ nl,
    float* __restrict__ out)
{
    int gw = (blockIdx.x*blockDim.x + threadIdx.x) >> 5;
    int lane = threadIdx.x & 31;
    int base = gw*4;                       // 4 consecutive rows; never straddles pos/neg
    bool is_pos = (base < BB);
    int relbase = base - BB;

    const float* ain[4];
    const float* aout[4];
    bool ei[4], ep[4];
    int iidr[4], pidr[4];

    #pragma unroll
    for (int r = 0; r < 4; r++) {
        int rr = base + r;
        int i    = is_pos ? rr : ((relbase + r) >> 3);
        int plab = is_pos ? __ldg(pl + rr) : __ldg(nl + relbase + r);
        int ilab = __ldg(inl + i);
        ei[r] = ilab < ENT;
        ep[r] = plab < ENT;
        int iid = ei[r] ? ilab : (ilab - ENT);
        int pid = ep[r] ? plab : (plab - ENT);
        iidr[r] = min(iid, RELN - 1);
        pidr[r] = min(pid, RELN - 1);
        ain[r]  = ei[r] ? (ie + (long)iid*D) : (ir + iidr[r]*D);
        aout[r] = ep[r] ? (oe + (long)pid*D) : (orr + pidr[r]*D);
    }

    // issue all 8 gathers back-to-back (independent -> MLP 8)
    float4 vin[4], vout[4];
    #pragma unroll
    for (int r = 0; r < 4; r++) vin[r]  = ld4(ain[r], lane);
    #pragma unroll
    for (int r = 0; r < 4; r++) vout[r] = ld4(aout[r], lane);

    // rare projection fixups (warp-uniform branches, taken ~0.05% of the time)
    #pragma unroll
    for (int r = 0; r < 4; r++) {
        if (ei[r] && !ep[r]) vin[r]  = map4(vin[r],  ld4(im + pidr[r]*D, lane));
        if (ep[r] && !ei[r]) vout[r] = map4(vout[r], ld4(om + iidr[r]*D, lane));
    }

    float d0 = warpsum(vin[0].x*vout[0].x + vin[0].y*vout[0].y + vin[0].z*vout[0].z + vin[0].w*vout[0].w);
    float d1 = warpsum(vin[1].x*vout[1].x + vin[1].y*vout[1].y + vin[1].z*vout[1].z + vin[1].w*vout[1].w);
    float d2 = warpsum(vin[2].x*vout[2].x + vin[2].y*vout[2].y + vin[2].z*vout[2].z + vin[2].w*vout[2].w);
    float d3 = warpsum(vin[3].x*vout[3].x + vin[3].y*vout[3].y + vin[3].z*vout[3].z + vin[3].w*vout[3].w);

    if (lane < 4) {
        float dd = (lane == 0) ? d0 : (lane == 1) ? d1 : (lane == 2) ? d2 : d3;
        int rr = base + lane;
        float x = is_pos ? dd : -dd;
        float ls = fminf(x, 0.0f) - log1pf(expf(-fabsf(x)));
        int tgt;
        if (is_pos) {
            unsigned v = g_cr_pos[rr];
            tgt = g_off_pos[(rr >> 10)*4 + (v >> 12)] + (v & 0xFFF);
        } else {
            int r2 = rr - BB;
            unsigned v = g_cr_neg[r2];
            int s = g_off_neg[(r2 >> 10)*4 + (v >> 12)] + (v & 0xFFF);
            tgt = s >> 3;                          // reshape(b,k).sum(1)
        }
        atomicAdd(&out[tgt], -ls);
    }
}

extern "C" void kernel_launch(void* const* d_in, const int* in_sizes, int n_in,
                              void* d_out, int out_size)
{
    const float* ie  = (const float*)d_in[0];  // in_ent_w
    const float* oe  = (const float*)d_in[1];  // out_ent_w
    const float* ir  = (const float*)d_in[2];  // in_rel_w
    const float* orr = (const float*)d_in[3];  // out_rel_w
    const float* im  = (const float*)d_in[4];  // in_map_w
    const float* om  = (const float*)d_in[5];  // out_map_w
    const int* inl = (const int*)d_in[6];      // input_labels
    const int* pl  = (const int*)d_in[7];      // pos_labels
    const int* nl  = (const int*)d_in[8];      // neg_labels (B*K)
    float* out = (float*)d_out;

    k_prep<<<HBLK_POS + HBLK_NEG, 256>>>(inl, pl, nl, out);
    k_scan2<<<1, 256>>>();

    int total_warps = (BB + NNEG)/4;          // 73728 warps
    int blocks = total_warps/8;               // 9216 blocks of 256 threads
    k_dot<<<blocks, 256>>>(ie, oe, ir, orr, im, om, inl, pl, nl, out);
}

// round 6
// speedup vs baseline: 1.7748x; 1.3430x over previous
#include <cuda_runtime.h>
#include <cuda_bf16.h>
#include <math.h>

#define ENT 250000
#define RELN 64
#define D 128
#define BB 32768
#define KK 8
#define NNEG (BB*KK)

#define ROWS_PER_BLK 1024
#define HBLK_POS (BB/ROWS_PER_BLK)    // 32
#define HBLK_NEG (NNEG/ROWS_PER_BLK)  // 256

typedef unsigned long long u64;

// Scratch (device globals: no allocations allowed)
// packed per-row: (class << 12) | local_rank   (local_rank < 1024)
__device__ unsigned short g_cr_pos[BB];
__device__ unsigned short g_cr_neg[NNEG];
__device__ int g_hist_pos[HBLK_POS*4];
__device__ int g_hist_neg[HBLK_NEG*4];
__device__ int g_off_pos[HBLK_POS*4];
__device__ int g_off_neg[HBLK_NEG*4];

// ---------------------------------------------------------------------------
// K1: branch classification + per-block stable rank + per-block histogram.
// 256 threads/block, 4 rows/thread (1024 rows/block).
// Blocks [0, HBLK_POS) = pos rows (also zero `out`); rest = neg rows.
// ---------------------------------------------------------------------------
__global__ void __launch_bounds__(256) k_prep(
    const int* __restrict__ inl, const int* __restrict__ pl,
    const int* __restrict__ nl, float* __restrict__ out)
{
    int blk = blockIdx.x;
    bool is_pos = (blk < HBLK_POS);
    int t = threadIdx.x;
    int lane = t & 31, warp = t >> 5;

    int rowbase;
    int c[4];
    if (is_pos) {
        rowbase = blk*ROWS_PER_BLK + t*4;
        int4 il  = *reinterpret_cast<const int4*>(inl + rowbase);
        int4 plv = *reinterpret_cast<const int4*>(pl + rowbase);
        *reinterpret_cast<float4*>(out + rowbase) = make_float4(0.f,0.f,0.f,0.f);
        c[0] = ((il.x >= ENT) ? 2 : 0) + ((plv.x >= ENT) ? 1 : 0);
        c[1] = ((il.y >= ENT) ? 2 : 0) + ((plv.y >= ENT) ? 1 : 0);
        c[2] = ((il.z >= ENT) ? 2 : 0) + ((plv.z >= ENT) ? 1 : 0);
        c[3] = ((il.w >= ENT) ? 2 : 0) + ((plv.w >= ENT) ? 1 : 0);
    } else {
        rowbase = (blk - HBLK_POS)*ROWS_PER_BLK + t*4;
        int ilv = inl[rowbase >> 3];               // constant across the 4 rows
        int4 nlv = *reinterpret_cast<const int4*>(nl + rowbase);
        int ci = (ilv >= ENT) ? 2 : 0;
        c[0] = ci + ((nlv.x >= ENT) ? 1 : 0);
        c[1] = ci + ((nlv.y >= ENT) ? 1 : 0);
        c[2] = ci + ((nlv.z >= ENT) ? 1 : 0);
        c[3] = ci + ((nlv.w >= ENT) ? 1 : 0);
    }

    // per-thread packed class counts (4 classes x 16 bits)
    u64 cnt = 0;
    #pragma unroll
    for (int j = 0; j < 4; j++) cnt += 1ULL << (16*c[j]);

    // warp inclusive scan
    u64 s = cnt;
    #pragma unroll
    for (int d = 1; d < 32; d <<= 1) {
        u64 u = __shfl_up_sync(0xFFFFFFFFu, s, d);
        if (lane >= d) s += u;
    }
    u64 wexcl = s - cnt;

    __shared__ u64 wtot[8];
    __shared__ u64 wbase[8];
    __shared__ u64 btot;
    if (lane == 31) wtot[warp] = s;
    __syncthreads();
    if (t == 0) {
        u64 a = 0;
        #pragma unroll
        for (int i = 0; i < 8; i++) { u64 tv = wtot[i]; wbase[i] = a; a += tv; }
        btot = a;
    }
    __syncthreads();

    u64 excl = wexcl + wbase[warp];   // per-class exclusive offset for this thread

    // assign stable ranks to the 4 rows in order
    u64 outpk = 0;
    #pragma unroll
    for (int j = 0; j < 4; j++) {
        int cc = c[j];
        int rk = (int)((excl >> (16*cc)) & 0xFFFFULL);
        excl += 1ULL << (16*cc);
        outpk |= ((u64)((cc << 12) | rk)) << (16*j);
    }

    if (is_pos) {
        *reinterpret_cast<u64*>(g_cr_pos + rowbase) = outpk;
        if (t < 4) g_hist_pos[blk*4 + t] = (int)((btot >> (16*t)) & 0xFFFFULL);
    } else {
        *reinterpret_cast<u64*>(g_cr_neg + rowbase) = outpk;
        if (t < 4) g_hist_neg[(blk - HBLK_POS)*4 + t] = (int)((btot >> (16*t)) & 0xFFFFULL);
    }
}

// ---------------------------------------------------------------------------
// K2: one block scans BOTH histogram sets (neg: 256 entries, pos: 32).
// ---------------------------------------------------------------------------
__global__ void __launch_bounds__(256) k_scan2()
{
    int t = threadIdx.x, lane = t & 31, w = t >> 5;

    // ---- neg (256 entries) ----
    unsigned h0 = g_hist_neg[t*4+0], h1 = g_hist_neg[t*4+1];
    unsigned h2 = g_hist_neg[t*4+2], h3 = g_hist_neg[t*4+3];
    u64 ownA = (u64)h0 | ((u64)h1 << 32);
    u64 ownB = (u64)h2 | ((u64)h3 << 32);
    u64 A = ownA, B = ownB;
    #pragma unroll
    for (int d = 1; d < 32; d <<= 1) {
        u64 ua = __shfl_up_sync(0xFFFFFFFFu, A, d);
        u64 ub = __shfl_up_sync(0xFFFFFFFFu, B, d);
        if (lane >= d) { A += ua; B += ub; }
    }
    __shared__ u64 sA[8], sB[8];
    __shared__ u64 gTotA, gTotB;
    if (lane == 31) { sA[w] = A; sB[w] = B; }
    __syncthreads();
    if (t == 0) {
        u64 a = 0, b = 0;
        #pragma unroll
        for (int i = 0; i < 8; i++) {
            u64 ta = sA[i], tb = sB[i];
            sA[i] = a; sB[i] = b;
            a += ta; b += tb;
        }
        gTotA = a; gTotB = b;
    }
    __syncthreads();
    u64 excA = A + sA[w] - ownA;
    u64 excB = B + sB[w] - ownB;
    {
        unsigned n0 = (unsigned)(gTotA), n1 = (unsigned)(gTotA >> 32);
        unsigned n2 = (unsigned)(gTotB);
        int base0 = 0;
        int base1 = base0 + (int)n0;
        int base2 = base1 + (int)n1;
        int base3 = base2 + (int)n2;
        g_off_neg[t*4+0] = base0 + (int)(excA & 0xFFFFFFFFULL);
        g_off_neg[t*4+1] = base1 + (int)(excA >> 32);
        g_off_neg[t*4+2] = base2 + (int)(excB & 0xFFFFFFFFULL);
        g_off_neg[t*4+3] = base3 + (int)(excB >> 32);
    }

    // ---- pos (32 entries), warp 0 only ----
    if (w == 0) {
        unsigned p0 = g_hist_pos[lane*4+0], p1 = g_hist_pos[lane*4+1];
        unsigned p2 = g_hist_pos[lane*4+2], p3 = g_hist_pos[lane*4+3];
        u64 oA = (u64)p0 | ((u64)p1 << 32);
        u64 oB = (u64)p2 | ((u64)p3 << 32);
        u64 PA = oA, PB = oB;
        #pragma unroll
        for (int d = 1; d < 32; d <<= 1) {
            u64 ua = __shfl_up_sync(0xFFFFFFFFu, PA, d);
            u64 ub = __shfl_up_sync(0xFFFFFFFFu, PB, d);
            if (lane >= d) { PA += ua; PB += ub; }
        }
        u64 tA = __shfl_sync(0xFFFFFFFFu, PA, 31);
        u64 tB = __shfl_sync(0xFFFFFFFFu, PB, 31);
        u64 eA = PA - oA, eB = PB - oB;
        unsigned q0 = (unsigned)tA, q1 = (unsigned)(tA >> 32), q2 = (unsigned)tB;
        int base0 = 0;
        int base1 = base0 + (int)q0;
        int base2 = base1 + (int)q1;
        int base3 = base2 + (int)q2;
        g_off_pos[lane*4+0] = base0 + (int)(eA & 0xFFFFFFFFULL);
        g_off_pos[lane*4+1] = base1 + (int)(eA >> 32);
        g_off_pos[lane*4+2] = base2 + (int)(eB & 0xFFFFFFFFULL);
        g_off_pos[lane*4+3] = base3 + (int)(eB >> 32);
    }
}

// ---------------------------------------------------------------------------
// K3: dot kernel — ONE WARP PER BATCH ELEMENT i.
// Loads the in-side row once, gathers 1 pos + 8 neg out-rows (10 gathers,
// 9 dots). Lane = one float4 of the 128-dim vector.
// ---------------------------------------------------------------------------
__device__ __forceinline__ float warpsum(float v) {
    v += __shfl_xor_sync(0xFFFFFFFFu, v, 16);
    v += __shfl_xor_sync(0xFFFFFFFFu, v, 8);
    v += __shfl_xor_sync(0xFFFFFFFFu, v, 4);
    v += __shfl_xor_sync(0xFFFFFFFFu, v, 2);
    v += __shfl_xor_sync(0xFFFFFFFFu, v, 1);
    return v;
}

__device__ __forceinline__ float4 ld4(const float* base, int lane) {
    return reinterpret_cast<const float4*>(base)[lane];
}

// TransH projection: e - (e.n) n with n = m / max(||m||, 1e-12)
__device__ __forceinline__ float4 map4(float4 e, float4 m) {
    float mm = m.x*m.x + m.y*m.y + m.z*m.z + m.w*m.w;
    float em = e.x*m.x + e.y*m.y + e.z*m.z + e.w*m.w;
    mm = warpsum(mm);
    em = warpsum(em);
    float dn = fmaxf(sqrtf(mm), 1e-12f);
    float coef = em / (dn*dn);
    float4 r;
    r.x = e.x - coef*m.x;
    r.y = e.y - coef*m.y;
    r.z = e.z - coef*m.z;
    r.w = e.w - coef*m.w;
    return r;
}

__device__ __forceinline__ float dot4w(float4 a, float4 b) {
    return warpsum(a.x*b.x + a.y*b.y + a.z*b.z + a.w*b.w);
}

__global__ void __launch_bounds__(256) k_dot(
    const float* __restrict__ ie, const float* __restrict__ oe,
    const float* __restrict__ ir, const float* __restrict__ orr,
    const float* __restrict__ im, const float* __restrict__ om,
    const int* __restrict__ inl, const int* __restrict__ pl, const int* __restrict__ nl,
    float* __restrict__ out)
{
    int i = (blockIdx.x*blockDim.x + threadIdx.x) >> 5;   // batch element
    int lane = threadIdx.x & 31;

    int ilab = __ldg(inl + i);
    int plab = __ldg(pl + i);
    int nlab_l = (lane < KK) ? __ldg(nl + i*KK + lane) : 0;

    bool ei = ilab < ENT;
    int iid  = ei ? ilab : (ilab - ENT);
    int iid_r = min(iid, RELN - 1);
    const float* ain = ei ? (ie + (long)iid*D) : (ir + iid_r*D);
    const float* aom = om + iid_r*D;   // out-side projection row (rare path)

    bool ep = plab < ENT;
    int pid  = ep ? plab : (plab - ENT);
    int pid_r = min(pid, RELN - 1);
    const float* apos = ep ? (oe + (long)pid*D) : (orr + pid_r*D);

    bool en[KK];
    int nid_r[KK];
    const float* aneg[KK];
    #pragma unroll
    for (int r = 0; r < KK; r++) {
        int nlab = __shfl_sync(0xFFFFFFFFu, nlab_l, r);
        en[r] = nlab < ENT;
        int nid = en[r] ? nlab : (nlab - ENT);
        nid_r[r] = min(nid, RELN - 1);
        aneg[r] = en[r] ? (oe + (long)nid*D) : (orr + nid_r[r]*D);
    }

    // issue all 10 independent row gathers back-to-back (MLP=10)
    float4 vin  = ld4(ain, lane);
    float4 vpos = ld4(apos, lane);
    float4 vneg[KK];
    #pragma unroll
    for (int r = 0; r < KK; r++) vneg[r] = ld4(aneg[r], lane);

    // ---- pos pair (with rare projection fixups, warp-uniform) ----
    float4 vin_pos = vin;
    if (ei && !ep) vin_pos = map4(vin, ld4(im + pid_r*D, lane));
    float4 vout_pos = vpos;
    if (ep && !ei) vout_pos = map4(vpos, ld4(aom, lane));
    float dpos = dot4w(vin_pos, vout_pos);

    // ---- neg pairs ----
    float dneg[KK];
    #pragma unroll
    for (int r = 0; r < KK; r++) {
        float4 vi = vin;
        if (ei && !en[r]) vi = map4(vin, ld4(im + nid_r[r]*D, lane));
        float4 vo = vneg[r];
        if (en[r] && !ei) vo = map4(vneg[r], ld4(aom, lane));
        dneg[r] = dot4w(vi, vo);
    }

    // ---- epilogue: lane 0 = pos row, lanes 1..8 = neg rows ----
    if (lane <= KK) {
        float x;
        int tgt;
        if (lane == 0) {
            x = dpos;
            unsigned v = g_cr_pos[i];
            tgt = g_off_pos[(i >> 10)*4 + (v >> 12)] + (v & 0xFFF);
        } else {
            int r = lane - 1;
            float dd = dneg[0];
            #pragma unroll
            for (int q = 1; q < KK; q++) if (r == q) dd = dneg[q];
            x = -dd;
            int j = i*KK + r;
            unsigned v = g_cr_neg[j];
            int s = g_off_neg[(j >> 10)*4 + (v >> 12)] + (v & 0xFFF);
            tgt = s >> 3;                      // reshape(b,k).sum(1)
        }
        float ls = fminf(x, 0.0f) - log1pf(expf(-fabsf(x)));
        atomicAdd(&out[tgt], -ls);
    }
}

extern "C" void kernel_launch(void* const* d_in, const int* in_sizes, int n_in,
                              void* d_out, int out_size)
{
    const float* ie  = (const float*)d_in[0];  // in_ent_w
    const float* oe  = (const float*)d_in[1];  // out_ent_w
    const float* ir  = (const float*)d_in[2];  // in_rel_w
    const float* orr = (const float*)d_in[3];  // out_rel_w
    const float* im  = (const float*)d_in[4];  // in_map_w
    const float* om  = (const float*)d_in[5];  // out_map_w
    const int* inl = (const int*)d_in[6];      // input_labels
    const int* pl  = (const int*)d_in[7];      // pos_labels
    const int* nl  = (const int*)d_in[8];      // neg_labels (B*K)
    float* out = (float*)d_out;

    k_prep<<<HBLK_POS + HBLK_NEG, 256>>>(inl, pl, nl, out);
    k_scan2<<<1, 256>>>();

    int blocks = BB/8;                        // 32768 warps, 8 per block
    k_dot<<<blocks, 256>>>(ie, oe, ir, orr, im, om, inl, pl, nl, out);
}